// round 16
// baseline (speedup 1.0000x reference)
#include <cuda_runtime.h>
#include <cuda_fp16.h>
#include <cstdint>

#define NSLOTS 8
#define NKEYS  8192
#define KDIM   256
#define VDIM   512
#define NQ     4096
#define IN_DIM 512
#define TOPK   32
#define QT     64                     // queries per block
#define NCHUNK 64                     // chunks of 128 keys
#define NSTAGE 256

__device__ float  g_q[NQ * KDIM];                      // 4 MB fp32 (exact)
__device__ float  g_resid[NQ * VDIM];                  // 8 MB fp32 (exact)
__device__ __half g_keysf[NSLOTS * NKEYS * KDIM];      // 33.5 MB keys in B-fragment order
__device__ __half g_valh[NSLOTS * NKEYS * VDIM];       // 67 MB fp16 values

// ---------------------------------------------------------------------------
// fp32 GEMM (NT): C = A·Bᵀ + bias. BM=64,BN=64,BK=16,TM=8,TN=4, 128 thr.
// ---------------------------------------------------------------------------
__global__ __launch_bounds__(128) void gemm_nt_bias(
    const float* __restrict__ A, const float* __restrict__ B,
    const float* __restrict__ bias, float* __restrict__ C,
    int M, int N, int K)
{
    __shared__ float As[16][68];
    __shared__ float Bs[16][68];
    const int tid = threadIdx.x;
    const int tx = tid & 15, ty = tid >> 4;
    const int m0 = blockIdx.y * 64, n0 = blockIdx.x * 64;

    float acc[8][4];
#pragma unroll
    for (int i = 0; i < 8; i++)
#pragma unroll
        for (int j = 0; j < 4; j++) acc[i][j] = 0.f;

    for (int k0 = 0; k0 < K; k0 += 16) {
        __syncthreads();
#pragma unroll
        for (int i = 0; i < 2; i++) {
            int f = tid + i * 128;
            int r = f >> 2, q4 = (f & 3) << 2;
            float4 va = *(const float4*)(A + (size_t)(m0 + r) * K + k0 + q4);
            As[q4 + 0][r] = va.x; As[q4 + 1][r] = va.y;
            As[q4 + 2][r] = va.z; As[q4 + 3][r] = va.w;
            float4 vb = *(const float4*)(B + (size_t)(n0 + r) * K + k0 + q4);
            Bs[q4 + 0][r] = vb.x; Bs[q4 + 1][r] = vb.y;
            Bs[q4 + 2][r] = vb.z; Bs[q4 + 3][r] = vb.w;
        }
        __syncthreads();
#pragma unroll
        for (int k = 0; k < 16; k++) {
            float4 a0 = *(const float4*)&As[k][ty * 8];
            float4 a1 = *(const float4*)&As[k][ty * 8 + 4];
            float4 b  = *(const float4*)&Bs[k][tx * 4];
            float av[8] = {a0.x, a0.y, a0.z, a0.w, a1.x, a1.y, a1.z, a1.w};
            float bv[4] = {b.x, b.y, b.z, b.w};
#pragma unroll
            for (int i = 0; i < 8; i++)
#pragma unroll
                for (int j = 0; j < 4; j++) acc[i][j] += av[i] * bv[j];
        }
    }
    const int n = n0 + tx * 4;
    float4 bb = *(const float4*)(bias + n);
#pragma unroll
    for (int i = 0; i < 8; i++) {
        float4 o = make_float4(acc[i][0] + bb.x, acc[i][1] + bb.y,
                               acc[i][2] + bb.z, acc[i][3] + bb.w);
        *(float4*)(C + (size_t)(m0 + ty * 8 + i) * N + n) = o;
    }
}

// ---------------------------------------------------------------------------
// prep: (a) keys -> normalized fp16 in B-FRAGMENT order, (b) values -> fp16
// ---------------------------------------------------------------------------
__global__ __launch_bounds__(256) void prep(
    const float* __restrict__ keys, const float* __restrict__ values,
    __half* __restrict__ kf, __half* __restrict__ vh)
{
    if (blockIdx.x < 8192) {
        __shared__ __half h[8][264];
        const int lane = threadIdx.x & 31;
        const int warp = threadIdx.x >> 5;
        const int key = blockIdx.x * 8 + warp;
        const float4* kp4 = (const float4*)(keys + (size_t)key * KDIM);
        float4 v0 = kp4[2 * lane], v1 = kp4[2 * lane + 1];
        float s = v0.x * v0.x + v0.y * v0.y + v0.z * v0.z + v0.w * v0.w
                + v1.x * v1.x + v1.y * v1.y + v1.z * v1.z + v1.w * v1.w;
#pragma unroll
        for (int o = 16; o; o >>= 1) s += __shfl_xor_sync(0xffffffffu, s, o);
        float inv = rsqrtf(s);
        __half2 p0 = __floats2half2_rn(v0.x * inv, v0.y * inv);
        __half2 p1 = __floats2half2_rn(v0.z * inv, v0.w * inv);
        __half2 p2 = __floats2half2_rn(v1.x * inv, v1.y * inv);
        __half2 p3 = __floats2half2_rn(v1.z * inv, v1.w * inv);
        *(uint4*)&h[warp][8 * lane] = make_uint4(
            *(unsigned*)&p0, *(unsigned*)&p1, *(unsigned*)&p2, *(unsigned*)&p3);
        __syncwarp();

        const int ss = lane >> 3, kpp = (lane >> 2) & 1, m = lane & 3;
        const int base = ss * 64 + kpp * 32 + 2 * m;
        __half2 q0 = __halves2half2(h[warp][base],      h[warp][base + 1]);
        __half2 q1 = __halves2half2(h[warp][base + 8],  h[warp][base + 9]);
        __half2 q2 = __halves2half2(h[warp][base + 16], h[warp][base + 17]);
        __half2 q3 = __halves2half2(h[warp][base + 24], h[warp][base + 25]);
        uint4 word = make_uint4(*(unsigned*)&q0, *(unsigned*)&q1,
                                *(unsigned*)&q2, *(unsigned*)&q3);

        const int slot = key >> 13, kk = key & 8191;
        const int chunk = kk >> 7, nn = (kk & 127) >> 3, nk = kk & 7;
        size_t unit = (size_t)slot * 262144
                    + ((size_t)((chunk * 4 + ss) * 16 + nn) * 2 + kpp) * 32
                    + (nk * 4 + m);
        ((uint4*)kf)[unit] = word;
    } else {
        size_t i = ((size_t)(blockIdx.x - 8192) * 256 + threadIdx.x) * 8;
        float4 a = *(const float4*)(values + i);
        float4 b = *(const float4*)(values + i + 4);
        __half2 p0 = __floats2half2_rn(a.x, a.y);
        __half2 p1 = __floats2half2_rn(a.z, a.w);
        __half2 p2 = __floats2half2_rn(b.x, b.y);
        __half2 p3 = __floats2half2_rn(b.z, b.w);
        *(uint4*)(vh + i) = make_uint4(*(unsigned*)&p0, *(unsigned*)&p1,
                                       *(unsigned*)&p2, *(unsigned*)&p3);
    }
}

// ---------------------------------------------------------------------------
__device__ __forceinline__ void mma_f16(float c[4],
    unsigned a0, unsigned a1, unsigned a2, unsigned a3,
    unsigned b0, unsigned b1)
{
    asm volatile(
        "mma.sync.aligned.m16n8k16.row.col.f32.f16.f16.f32 "
        "{%0,%1,%2,%3}, {%4,%5,%6,%7}, {%8,%9}, {%0,%1,%2,%3};"
        : "+f"(c[0]), "+f"(c[1]), "+f"(c[2]), "+f"(c[3])
        : "r"(a0), "r"(a1), "r"(a2), "r"(a3), "r"(b0), "r"(b1));
}

__device__ __forceinline__ void ldsm4(unsigned r[4], uint32_t addr) {
    asm volatile("ldmatrix.sync.aligned.m8n8.x4.shared.b16 {%0,%1,%2,%3}, [%4];"
                 : "=r"(r[0]), "=r"(r[1]), "=r"(r[2]), "=r"(r[3]) : "r"(addr));
}

// packed score|idx (order-preserving), 19 score bits + 13 index bits
__device__ __forceinline__ unsigned packscore(float f, int idx) {
    unsigned u = __float_as_uint(f);
    u = ((int)u >= 0) ? (u | 0x80000000u) : ~u;
    return (u & 0xFFFFE000u) | (unsigned)idx;
}
__device__ __forceinline__ float unpackscore(unsigned p) {
    unsigned bits = (p & 0x80000000u) ? (p & 0x7FFFFFFFu) : ~p;
    bits = (bits & 0xFFFFE000u) | 0x1000u;
    return __uint_as_float(bits);
}

// branch-free min rescan over 32-slot flat list
__device__ __forceinline__ void rescan32(const unsigned* h, unsigned& hmin, int& minpos) {
    unsigned m = h[0]; int p = 0;
#pragma unroll
    for (int i = 1; i < 32; i++) {
        unsigned x = h[i];
        if (x < m) { m = x; p = i; }
    }
    hmin = m; minpos = p;
}

#define BAR_SYNC(id, cnt)   asm volatile("bar.sync %0, %1;"   :: "r"(id), "r"(cnt) : "memory")
#define BAR_ARRIVE(id, cnt) asm volatile("bar.arrive %0, %1;" :: "r"(id), "r"(cnt) : "memory")

// ---------------------------------------------------------------------------
// smem layout: sQ 33792 | sv 65536 | cnt 512 | hminS 256 | hp 8448 = 108544
// ---------------------------------------------------------------------------
#define SQ_STRIDE_B 528
#define SV_OFF    33792
#define SV_BUF    (QT * 128)
#define CNT_OFF   (SV_OFF + 2 * SV_BUF * 4)    // 99328
#define HMIN_OFF  (CNT_OFF + 2 * QT * 4)       // 99840
#define HP_OFF    (HMIN_OFF + QT * 4)          // 100096
#define FUSED_SMEM_BYTES (HP_OFF + QT * 33 * 4)   // 108544
#define NTHREADS 320

__global__ __launch_bounds__(NTHREADS, 2) void fused_slot(
    const __half* __restrict__ keysf, const __half* __restrict__ valh,
    float* __restrict__ out)
{
    extern __shared__ char smem[];
    const uint32_t sb = (uint32_t)__cvta_generic_to_shared(smem);
    __half* sQ = (__half*)smem;
    unsigned* sv    = (unsigned*)(smem + SV_OFF);
    unsigned* cnt   = (unsigned*)(smem + CNT_OFF);
    unsigned* hminS = (unsigned*)(smem + HMIN_OFF);
    unsigned* hp    = (unsigned*)(smem + HP_OFF);

    const int tid  = threadIdx.x;
    const int lane = tid & 31, wid = tid >> 5;     // wid 0..7 MMA, 8..9 scan
    const int g = lane >> 2, tig = lane & 3;
    const int slot = blockIdx.y;
    const int q0 = blockIdx.x * QT;

    // ---- setup ----
    if (tid < 256) {
        const float4* qg4 = (const float4*)(g_q + (size_t)q0 * KDIM);
#pragma unroll
        for (int i = 0; i < 16; i++) {
            int f = tid + i * 256;
            int row = f >> 6, c4 = (f & 63) << 2;
            float4 v = qg4[f];
            __half2 h0 = __floats2half2_rn(v.x, v.y);
            __half2 h1 = __floats2half2_rn(v.z, v.w);
            *(uint2*)(sQ + row * 264 + c4) = make_uint2(*(unsigned*)&h0, *(unsigned*)&h1);
        }
    } else {
        const int s0 = tid - 256;                  // 0..63
        for (int i = s0; i < QT * 33; i += 64) hp[i] = 0u;
        cnt[s0] = 0u; cnt[64 + s0] = 0u;
        hminS[s0] = 0u;
    }
    __syncthreads();

    if (wid < 8) {
        // ================== MMA warps: 2x4 tiling (32q x 32k) ==================
        const int warp_m = wid >> 2;               // 0..1
        const int warp_n = wid & 3;                // 0..3
        const uint4* kb = (const uint4*)(keysf + (size_t)slot * NKEYS * KDIM);
        const uint4* kwarp = kb + warp_n * 256 + lane;
        const int lrow = (lane & 7) + ((lane >> 3) & 1) * 8;
        const int lcolb = (lane >> 4) * 16;
        const uint32_t aBase = sb + (uint32_t)((warp_m * 32 + lrow) * SQ_STRIDE_B) + lcolb;

        float c[2][4][4];
#pragma unroll
        for (int mm = 0; mm < 2; mm++)
#pragma unroll
            for (int nn = 0; nn < 4; nn++)
#pragma unroll
                for (int r = 0; r < 4; r++) c[mm][nn][r] = 0.f;

        // half-stage B buffers: bufA = kp0, bufB = kp1
        uint4 bufA[4], bufB[4];
#pragma unroll
        for (int nnl = 0; nnl < 4; nnl++) bufA[nnl] = kwarp[nnl * 64];   // (t=0, kp0)

        for (int cc = 0; cc < NCHUNK; cc++) {
#pragma unroll
            for (int s = 0; s < 4; s++) {
                const int t = cc * 4 + s;
                const uint32_t aCol = (uint32_t)s * 128;

                // ---- half 0: prefetch (t, kp1); compute ks=0,1 from bufA ----
#pragma unroll
                for (int nnl = 0; nnl < 4; nnl++)
                    bufB[nnl] = kwarp[t * 1024 + nnl * 64 + 32];
                {
                    unsigned A[2][2][4];
#pragma unroll
                    for (int mm = 0; mm < 2; mm++)
#pragma unroll
                        for (int k2 = 0; k2 < 2; k2++)
                            ldsm4(A[mm][k2], aBase + (uint32_t)(mm * 16 * SQ_STRIDE_B)
                                               + aCol + (uint32_t)k2 * 32);
#pragma unroll
                    for (int k2 = 0; k2 < 2; k2++)
#pragma unroll
                        for (int nnl = 0; nnl < 4; nnl++) {
                            unsigned b0 = k2 ? bufA[nnl].z : bufA[nnl].x;
                            unsigned b1 = k2 ? bufA[nnl].w : bufA[nnl].y;
#pragma unroll
                            for (int mm = 0; mm < 2; mm++)
                                mma_f16(c[mm][nnl], A[mm][k2][0], A[mm][k2][1],
                                        A[mm][k2][2], A[mm][k2][3], b0, b1);
                        }
                }
                // ---- half 1: prefetch (t+1, kp0); compute ks=2,3 from bufB ----
                const int tn = (t + 1 < NSTAGE) ? t + 1 : t;   // clamp (last never used)
#pragma unroll
                for (int nnl = 0; nnl < 4; nnl++)
                    bufA[nnl] = kwarp[tn * 1024 + nnl * 64];
                {
                    unsigned A[2][2][4];
#pragma unroll
                    for (int mm = 0; mm < 2; mm++)
#pragma unroll
                        for (int k2 = 0; k2 < 2; k2++)
                            ldsm4(A[mm][k2], aBase + (uint32_t)(mm * 16 * SQ_STRIDE_B)
                                               + aCol + 64 + (uint32_t)k2 * 32);
#pragma unroll
                    for (int k2 = 0; k2 < 2; k2++)
#pragma unroll
                        for (int nnl = 0; nnl < 4; nnl++) {
                            unsigned b0 = k2 ? bufB[nnl].z : bufB[nnl].x;
                            unsigned b1 = k2 ? bufB[nnl].w : bufB[nnl].y;
#pragma unroll
                            for (int mm = 0; mm < 2; mm++)
                                mma_f16(c[mm][nnl], A[mm][k2][0], A[mm][k2][1],
                                        A[mm][k2][2], A[mm][k2][3], b0, b1);
                        }
                }
            }

            // ---- chunk complete: pack in place, count, 1 atomic, store ----
            {
                const int p = cc & 1;
                const int key0 = cc << 7;
                if (cc >= 2) BAR_SYNC(3 + p, NTHREADS);     // scan(cc-2) done
                unsigned* svp  = sv + p * SV_BUF;
                unsigned* cntp = cnt + p * QT;
                const int cb = warp_n * 32;
#pragma unroll
                for (int mm = 0; mm < 2; mm++) {
                    const int r0 = warp_m * 32 + mm * 16 + g, r1 = r0 + 8;
                    const unsigned th0 = hminS[r0];
                    const unsigned th1 = hminS[r1];
                    // pass 1: pack scores in place (reuse acc registers), count
                    int n0 = 0, n1 = 0;
#pragma unroll
                    for (int nnl = 0; nnl < 4; nnl++) {
                        const int col = cb + nnl * 8 + 2 * tig;
                        unsigned v0 = packscore(c[mm][nnl][0], key0 + col);
                        unsigned v1 = packscore(c[mm][nnl][1], key0 + col + 1);
                        unsigned v2 = packscore(c[mm][nnl][2], key0 + col);
                        unsigned v3 = packscore(c[mm][nnl][3], key0 + col + 1);
                        c[mm][nnl][0] = __uint_as_float(v0);
                        c[mm][nnl][1] = __uint_as_float(v1);
                        c[mm][nnl][2] = __uint_as_float(v2);
                        c[mm][nnl][3] = __uint_as_float(v3);
                        n0 += (v0 > th0) + (v1 > th0);
                        n1 += (v2 > th1) + (v3 > th1);
                    }
                    if (n0 | n1) {
                        unsigned ix0 = 0, ix1 = 0;
                        if (n0) ix0 = atomicAdd(&cntp[r0], (unsigned)n0);
                        if (n1) ix1 = atomicAdd(&cntp[r1], (unsigned)n1);
                        // pass 2: store packed survivors from registers
#pragma unroll
                        for (int nnl = 0; nnl < 4; nnl++) {
                            unsigned v0 = __float_as_uint(c[mm][nnl][0]);
                            if (v0 > th0) svp[r0 * 128 + ix0++] = v0;
                            unsigned v1 = __float_as_uint(c[mm][nnl][1]);
                            if (v1 > th0) svp[r0 * 128 + ix0++] = v1;
                            unsigned v2 = __float_as_uint(c[mm][nnl][2]);
                            if (v2 > th1) svp[r1 * 128 + ix1++] = v2;
                            unsigned v3 = __float_as_uint(c[mm][nnl][3]);
                            if (v3 > th1) svp[r1 * 128 + ix1++] = v3;
                        }
                    }
                    // reset accumulators
#pragma unroll
                    for (int nnl = 0; nnl < 4; nnl++)
#pragma unroll
                        for (int r = 0; r < 4; r++) c[mm][nnl][r] = 0.f;
                }
                __threadfence_block();
                BAR_ARRIVE(1 + p, NTHREADS);                 // survivors(cc) ready
            }
        }
    } else {
        // =========================== scan warps ==========================
        const int q = tid - 256;                   // 0..63
        unsigned* h = hp + q * 33;
        unsigned hmin = 0; int minpos = 0;

        for (int cc = 0; cc < NCHUNK; cc++) {
            const int p = cc & 1;
            BAR_SYNC(1 + p, NTHREADS);             // survivors(cc) ready
            const int n = (int)cnt[p * QT + q];
            const unsigned* s = sv + p * SV_BUF + q * 128;
            for (int i = 0; i < n; i++) {
                unsigned v = s[i];
                if (v > hmin) { h[minpos] = v; rescan32(h, hmin, minpos); }
            }
            cnt[p * QT + q] = 0u;
            hminS[q] = hmin;
            __threadfence_block();
            BAR_ARRIVE(3 + p, NTHREADS);           // buffer p free
        }
    }
    __syncthreads();

    // ---- softmax over top-32 + fp16 value gather + fp32 residual ----
    // all 10 warps: q = wid, wid+10, ...
    {
        const __half* vbase = valh + (size_t)slot * NKEYS * VDIM;
        for (int q = wid; q < QT; q += 10) {
            const int qg_ = q0 + q;
            unsigned p = hp[q * 33 + lane];
            float s = unpackscore(p);
            int  ki = (int)(p & 0x1FFFu);
            float m = s;
#pragma unroll
            for (int o = 16; o; o >>= 1)
                m = fmaxf(m, __shfl_xor_sync(0xffffffffu, m, o));
            float e = __expf(s - m);
            float sum = e;
#pragma unroll
            for (int o = 16; o; o >>= 1) sum += __shfl_xor_sync(0xffffffffu, sum, o);
            float w = e / sum;

            float2 acc[2][4];
#pragma unroll
            for (int j = 0; j < 2; j++)
#pragma unroll
                for (int u = 0; u < 4; u++) acc[j][u] = make_float2(0.f, 0.f);

#pragma unroll 4
            for (int k = 0; k < TOPK; k++) {
                float wk = __shfl_sync(0xffffffffu, w, k);
                int   ik = __shfl_sync(0xffffffffu, ki, k);
                const uint4* vr = (const uint4*)(vbase + (size_t)ik * VDIM);
#pragma unroll
                for (int j = 0; j < 2; j++) {
                    uint4 u4 = vr[lane + j * 32];
                    unsigned uu[4] = {u4.x, u4.y, u4.z, u4.w};
#pragma unroll
                    for (int u = 0; u < 4; u++) {
                        float2 f = __half22float2(*(__half2*)&uu[u]);
                        acc[j][u].x += wk * f.x;
                        acc[j][u].y += wk * f.y;
                    }
                }
            }
            const float2* rr = (const float2*)(g_resid + (size_t)qg_ * VDIM);
            float2* op = (float2*)(out + ((size_t)qg_ * NSLOTS + slot) * VDIM);
#pragma unroll
            for (int j = 0; j < 2; j++)
#pragma unroll
                for (int u = 0; u < 4; u++) {
                    int idx = (lane + j * 32) * 4 + u;
                    float2 r = rr[idx];
                    op[idx] = make_float2(acc[j][u].x + r.x, acc[j][u].y + r.y);
                }
        }
    }
}

// ---------------------------------------------------------------------------
extern "C" void kernel_launch(void* const* d_in, const int* in_sizes, int n_in,
                              void* d_out, int out_size)
{
    const float* x      = (const float*)d_in[0];
    const float* keys   = (const float*)d_in[1];
    const float* values = (const float*)d_in[2];
    const float* wq     = (const float*)d_in[3];
    const float* bq     = (const float*)d_in[4];
    const float* wr     = (const float*)d_in[5];
    const float* br     = (const float*)d_in[6];
    float* out = (float*)d_out;

    float *qp, *rp;
    __half *kf, *vh;
    cudaGetSymbolAddress((void**)&qp, g_q);
    cudaGetSymbolAddress((void**)&rp, g_resid);
    cudaGetSymbolAddress((void**)&kf, g_keysf);
    cudaGetSymbolAddress((void**)&vh, g_valh);

    prep<<<8192 + NSLOTS * NKEYS * VDIM / (256 * 8), 256>>>(keys, values, kf, vh);
    gemm_nt_bias<<<dim3(KDIM / 64, NQ / 64), 128>>>(x, wq, bq, qp, NQ, KDIM, IN_DIM);
    gemm_nt_bias<<<dim3(VDIM / 64, NQ / 64), 128>>>(qp, wr, br, rp, NQ, VDIM, KDIM);

    cudaFuncSetAttribute(fused_slot,
                         cudaFuncAttributeMaxDynamicSharedMemorySize,
                         FUSED_SMEM_BYTES);
    fused_slot<<<dim3(NQ / QT, NSLOTS), NTHREADS, FUSED_SMEM_BYTES>>>(kf, vh, out);
}

// round 17
// speedup vs baseline: 1.5340x; 1.5340x over previous
#include <cuda_runtime.h>
#include <cuda_fp16.h>
#include <cstdint>

#define NSLOTS 8
#define NKEYS  8192
#define KDIM   256
#define VDIM   512
#define NQ     4096
#define IN_DIM 512
#define TOPK   32
#define QT     64                     // queries per block
#define NCHUNK 64                     // chunks of 128 keys
#define NSTAGE 256

__device__ float  g_q[NQ * KDIM];                      // 4 MB fp32 (exact)
__device__ float  g_resid[NQ * VDIM];                  // 8 MB fp32 (exact)
__device__ __half g_keysf[NSLOTS * NKEYS * KDIM];      // 33.5 MB keys in B-fragment order
__device__ __half g_valh[NSLOTS * NKEYS * VDIM];       // 67 MB fp16 values

// ---------------------------------------------------------------------------
// fp32 GEMM (NT): C = A·Bᵀ + bias. BM=64,BN=64,BK=16,TM=8,TN=4, 128 thr.
// ---------------------------------------------------------------------------
__global__ __launch_bounds__(128) void gemm_nt_bias(
    const float* __restrict__ A, const float* __restrict__ B,
    const float* __restrict__ bias, float* __restrict__ C,
    int M, int N, int K)
{
    __shared__ float As[16][68];
    __shared__ float Bs[16][68];
    const int tid = threadIdx.x;
    const int tx = tid & 15, ty = tid >> 4;
    const int m0 = blockIdx.y * 64, n0 = blockIdx.x * 64;

    float acc[8][4];
#pragma unroll
    for (int i = 0; i < 8; i++)
#pragma unroll
        for (int j = 0; j < 4; j++) acc[i][j] = 0.f;

    for (int k0 = 0; k0 < K; k0 += 16) {
        __syncthreads();
#pragma unroll
        for (int i = 0; i < 2; i++) {
            int f = tid + i * 128;
            int r = f >> 2, q4 = (f & 3) << 2;
            float4 va = *(const float4*)(A + (size_t)(m0 + r) * K + k0 + q4);
            As[q4 + 0][r] = va.x; As[q4 + 1][r] = va.y;
            As[q4 + 2][r] = va.z; As[q4 + 3][r] = va.w;
            float4 vb = *(const float4*)(B + (size_t)(n0 + r) * K + k0 + q4);
            Bs[q4 + 0][r] = vb.x; Bs[q4 + 1][r] = vb.y;
            Bs[q4 + 2][r] = vb.z; Bs[q4 + 3][r] = vb.w;
        }
        __syncthreads();
#pragma unroll
        for (int k = 0; k < 16; k++) {
            float4 a0 = *(const float4*)&As[k][ty * 8];
            float4 a1 = *(const float4*)&As[k][ty * 8 + 4];
            float4 b  = *(const float4*)&Bs[k][tx * 4];
            float av[8] = {a0.x, a0.y, a0.z, a0.w, a1.x, a1.y, a1.z, a1.w};
            float bv[4] = {b.x, b.y, b.z, b.w};
#pragma unroll
            for (int i = 0; i < 8; i++)
#pragma unroll
                for (int j = 0; j < 4; j++) acc[i][j] += av[i] * bv[j];
        }
    }
    const int n = n0 + tx * 4;
    float4 bb = *(const float4*)(bias + n);
#pragma unroll
    for (int i = 0; i < 8; i++) {
        float4 o = make_float4(acc[i][0] + bb.x, acc[i][1] + bb.y,
                               acc[i][2] + bb.z, acc[i][3] + bb.w);
        *(float4*)(C + (size_t)(m0 + ty * 8 + i) * N + n) = o;
    }
}

// ---------------------------------------------------------------------------
// prep: (a) keys -> normalized fp16 in B-FRAGMENT order, (b) values -> fp16
// ---------------------------------------------------------------------------
__global__ __launch_bounds__(256) void prep(
    const float* __restrict__ keys, const float* __restrict__ values,
    __half* __restrict__ kf, __half* __restrict__ vh)
{
    if (blockIdx.x < 8192) {
        __shared__ __half h[8][264];
        const int lane = threadIdx.x & 31;
        const int warp = threadIdx.x >> 5;
        const int key = blockIdx.x * 8 + warp;
        const float4* kp4 = (const float4*)(keys + (size_t)key * KDIM);
        float4 v0 = kp4[2 * lane], v1 = kp4[2 * lane + 1];
        float s = v0.x * v0.x + v0.y * v0.y + v0.z * v0.z + v0.w * v0.w
                + v1.x * v1.x + v1.y * v1.y + v1.z * v1.z + v1.w * v1.w;
#pragma unroll
        for (int o = 16; o; o >>= 1) s += __shfl_xor_sync(0xffffffffu, s, o);
        float inv = rsqrtf(s);
        __half2 p0 = __floats2half2_rn(v0.x * inv, v0.y * inv);
        __half2 p1 = __floats2half2_rn(v0.z * inv, v0.w * inv);
        __half2 p2 = __floats2half2_rn(v1.x * inv, v1.y * inv);
        __half2 p3 = __floats2half2_rn(v1.z * inv, v1.w * inv);
        *(uint4*)&h[warp][8 * lane] = make_uint4(
            *(unsigned*)&p0, *(unsigned*)&p1, *(unsigned*)&p2, *(unsigned*)&p3);
        __syncwarp();

        const int ss = lane >> 3, kpp = (lane >> 2) & 1, m = lane & 3;
        const int base = ss * 64 + kpp * 32 + 2 * m;
        __half2 q0 = __halves2half2(h[warp][base],      h[warp][base + 1]);
        __half2 q1 = __halves2half2(h[warp][base + 8],  h[warp][base + 9]);
        __half2 q2 = __halves2half2(h[warp][base + 16], h[warp][base + 17]);
        __half2 q3 = __halves2half2(h[warp][base + 24], h[warp][base + 25]);
        uint4 word = make_uint4(*(unsigned*)&q0, *(unsigned*)&q1,
                                *(unsigned*)&q2, *(unsigned*)&q3);

        const int slot = key >> 13, kk = key & 8191;
        const int chunk = kk >> 7, nn = (kk & 127) >> 3, nk = kk & 7;
        size_t unit = (size_t)slot * 262144
                    + ((size_t)((chunk * 4 + ss) * 16 + nn) * 2 + kpp) * 32
                    + (nk * 4 + m);
        ((uint4*)kf)[unit] = word;
    } else {
        size_t i = ((size_t)(blockIdx.x - 8192) * 256 + threadIdx.x) * 8;
        float4 a = *(const float4*)(values + i);
        float4 b = *(const float4*)(values + i + 4);
        __half2 p0 = __floats2half2_rn(a.x, a.y);
        __half2 p1 = __floats2half2_rn(a.z, a.w);
        __half2 p2 = __floats2half2_rn(b.x, b.y);
        __half2 p3 = __floats2half2_rn(b.z, b.w);
        *(uint4*)(vh + i) = make_uint4(*(unsigned*)&p0, *(unsigned*)&p1,
                                       *(unsigned*)&p2, *(unsigned*)&p3);
    }
}

// ---------------------------------------------------------------------------
__device__ __forceinline__ void mma_f16(float c[4],
    unsigned a0, unsigned a1, unsigned a2, unsigned a3,
    unsigned b0, unsigned b1)
{
    asm volatile(
        "mma.sync.aligned.m16n8k16.row.col.f32.f16.f16.f32 "
        "{%0,%1,%2,%3}, {%4,%5,%6,%7}, {%8,%9}, {%0,%1,%2,%3};"
        : "+f"(c[0]), "+f"(c[1]), "+f"(c[2]), "+f"(c[3])
        : "r"(a0), "r"(a1), "r"(a2), "r"(a3), "r"(b0), "r"(b1));
}

__device__ __forceinline__ void ldsm4(unsigned r[4], uint32_t addr) {
    asm volatile("ldmatrix.sync.aligned.m8n8.x4.shared.b16 {%0,%1,%2,%3}, [%4];"
                 : "=r"(r[0]), "=r"(r[1]), "=r"(r[2]), "=r"(r[3]) : "r"(addr));
}

// packed score|idx (order-preserving), 19 score bits + 13 index bits
__device__ __forceinline__ unsigned packscore(float f, int idx) {
    unsigned u = __float_as_uint(f);
    u = ((int)u >= 0) ? (u | 0x80000000u) : ~u;
    return (u & 0xFFFFE000u) | (unsigned)idx;
}
__device__ __forceinline__ float unpackscore(unsigned p) {
    unsigned bits = (p & 0x80000000u) ? (p & 0x7FFFFFFFu) : ~p;
    bits = (bits & 0xFFFFE000u) | 0x1000u;
    return __uint_as_float(bits);
}

// branch-free min rescan over 32-slot flat list
__device__ __forceinline__ void rescan32(const unsigned* h, unsigned& hmin, int& minpos) {
    unsigned m = h[0]; int p = 0;
#pragma unroll
    for (int i = 1; i < 32; i++) {
        unsigned x = h[i];
        if (x < m) { m = x; p = i; }
    }
    hmin = m; minpos = p;
}

#define BAR_SYNC(id, cnt)   asm volatile("bar.sync %0, %1;"   :: "r"(id), "r"(cnt) : "memory")
#define BAR_ARRIVE(id, cnt) asm volatile("bar.arrive %0, %1;" :: "r"(id), "r"(cnt) : "memory")

// ---------------------------------------------------------------------------
// smem layout: sQ 33792 | sv 65536 | cnt 512 | hminS 256 | hp 8448 = 108544
// ---------------------------------------------------------------------------
#define SQ_STRIDE_B 528
#define SV_OFF    33792
#define SV_BUF    (QT * 128)
#define CNT_OFF   (SV_OFF + 2 * SV_BUF * 4)    // 99328
#define HMIN_OFF  (CNT_OFF + 2 * QT * 4)       // 99840
#define HP_OFF    (HMIN_OFF + QT * 4)          // 100096
#define FUSED_SMEM_BYTES (HP_OFF + QT * 33 * 4)   // 108544
#define NTHREADS 320

__global__ __launch_bounds__(NTHREADS, 2) void fused_slot(
    const __half* __restrict__ keysf, const __half* __restrict__ valh,
    float* __restrict__ out)
{
    extern __shared__ char smem[];
    const uint32_t sb = (uint32_t)__cvta_generic_to_shared(smem);
    __half* sQ = (__half*)smem;
    unsigned* sv    = (unsigned*)(smem + SV_OFF);
    unsigned* cnt   = (unsigned*)(smem + CNT_OFF);
    unsigned* hminS = (unsigned*)(smem + HMIN_OFF);
    unsigned* hp    = (unsigned*)(smem + HP_OFF);

    const int tid  = threadIdx.x;
    const int lane = tid & 31, wid = tid >> 5;     // wid 0..7 MMA, 8..9 scan
    const int g = lane >> 2, tig = lane & 3;
    const int slot = blockIdx.y;
    const int q0 = blockIdx.x * QT;

    // ---- setup ----
    if (tid < 256) {
        const float4* qg4 = (const float4*)(g_q + (size_t)q0 * KDIM);
#pragma unroll
        for (int i = 0; i < 16; i++) {
            int f = tid + i * 256;
            int row = f >> 6, c4 = (f & 63) << 2;
            float4 v = qg4[f];
            __half2 h0 = __floats2half2_rn(v.x, v.y);
            __half2 h1 = __floats2half2_rn(v.z, v.w);
            *(uint2*)(sQ + row * 264 + c4) = make_uint2(*(unsigned*)&h0, *(unsigned*)&h1);
        }
    } else {
        const int s0 = tid - 256;                  // 0..63
        for (int i = s0; i < QT * 33; i += 64) hp[i] = 0u;
        cnt[s0] = 0u; cnt[64 + s0] = 0u;
        hminS[s0] = 0u;
    }
    __syncthreads();

    if (wid < 8) {
        // ================== MMA warps: 2x4 tiling (32q x 32k) ==================
        const int warp_m = wid >> 2;               // 0..1
        const int warp_n = wid & 3;                // 0..3
        const uint4* kb = (const uint4*)(keysf + (size_t)slot * NKEYS * KDIM);
        const uint4* kwarp = kb + warp_n * 256 + lane;
        const int lrow = (lane & 7) + ((lane >> 3) & 1) * 8;
        const int lcolb = (lane >> 4) * 16;
        const uint32_t aBase = sb + (uint32_t)((warp_m * 32 + lrow) * SQ_STRIDE_B) + lcolb;

        float c[2][4][4];
#pragma unroll
        for (int mm = 0; mm < 2; mm++)
#pragma unroll
            for (int nn = 0; nn < 4; nn++)
#pragma unroll
                for (int r = 0; r < 4; r++) c[mm][nn][r] = 0.f;

        // half-stage B buffers: bufA = kp0, bufB = kp1
        uint4 bufA[4], bufB[4];
#pragma unroll
        for (int nnl = 0; nnl < 4; nnl++) bufA[nnl] = kwarp[nnl * 64];   // (t=0, kp0)

        for (int cc = 0; cc < NCHUNK; cc++) {
#pragma unroll
            for (int s = 0; s < 4; s++) {
                const int t = cc * 4 + s;
                const uint32_t aCol = (uint32_t)s * 128;

                // ---- half 0: prefetch (t, kp1); compute ks=0,1 from bufA ----
#pragma unroll
                for (int nnl = 0; nnl < 4; nnl++)
                    bufB[nnl] = kwarp[t * 1024 + nnl * 64 + 32];
                {
                    unsigned A[2][2][4];
#pragma unroll
                    for (int mm = 0; mm < 2; mm++)
#pragma unroll
                        for (int k2 = 0; k2 < 2; k2++)
                            ldsm4(A[mm][k2], aBase + (uint32_t)(mm * 16 * SQ_STRIDE_B)
                                               + aCol + (uint32_t)k2 * 32);
#pragma unroll
                    for (int k2 = 0; k2 < 2; k2++)
#pragma unroll
                        for (int nnl = 0; nnl < 4; nnl++) {
                            unsigned b0 = k2 ? bufA[nnl].z : bufA[nnl].x;
                            unsigned b1 = k2 ? bufA[nnl].w : bufA[nnl].y;
#pragma unroll
                            for (int mm = 0; mm < 2; mm++)
                                mma_f16(c[mm][nnl], A[mm][k2][0], A[mm][k2][1],
                                        A[mm][k2][2], A[mm][k2][3], b0, b1);
                        }
                }
                // ---- half 1: prefetch (t+1, kp0); compute ks=2,3 from bufB ----
                const int tn = (t + 1 < NSTAGE) ? t + 1 : t;   // clamp (last never used)
#pragma unroll
                for (int nnl = 0; nnl < 4; nnl++)
                    bufA[nnl] = kwarp[tn * 1024 + nnl * 64];
                {
                    unsigned A[2][2][4];
#pragma unroll
                    for (int mm = 0; mm < 2; mm++)
#pragma unroll
                        for (int k2 = 0; k2 < 2; k2++)
                            ldsm4(A[mm][k2], aBase + (uint32_t)(mm * 16 * SQ_STRIDE_B)
                                               + aCol + 64 + (uint32_t)k2 * 32);
#pragma unroll
                    for (int k2 = 0; k2 < 2; k2++)
#pragma unroll
                        for (int nnl = 0; nnl < 4; nnl++) {
                            unsigned b0 = k2 ? bufB[nnl].z : bufB[nnl].x;
                            unsigned b1 = k2 ? bufB[nnl].w : bufB[nnl].y;
#pragma unroll
                            for (int mm = 0; mm < 2; mm++)
                                mma_f16(c[mm][nnl], A[mm][k2][0], A[mm][k2][1],
                                        A[mm][k2][2], A[mm][k2][3], b0, b1);
                        }
                }
            }

            // ---- chunk complete: count survivors, 1 atomic per row, store ----
            {
                const int p = cc & 1;
                const int key0 = cc << 7;
                if (cc >= 2) BAR_SYNC(3 + p, NTHREADS);     // scan(cc-2) done
                unsigned* svp  = sv + p * SV_BUF;
                unsigned* cntp = cnt + p * QT;
                const int cb = warp_n * 32;
#pragma unroll
                for (int mm = 0; mm < 2; mm++) {
                    const int r0 = warp_m * 32 + mm * 16 + g, r1 = r0 + 8;
                    const unsigned th0 = hminS[r0];
                    const unsigned th1 = hminS[r1];
                    // pass 1: count survivors per row
                    int n0 = 0, n1 = 0;
#pragma unroll
                    for (int nnl = 0; nnl < 4; nnl++) {
                        const int col = cb + nnl * 8 + 2 * tig;
                        n0 += (packscore(c[mm][nnl][0], key0 + col)     > th0);
                        n0 += (packscore(c[mm][nnl][1], key0 + col + 1) > th0);
                        n1 += (packscore(c[mm][nnl][2], key0 + col)     > th1);
                        n1 += (packscore(c[mm][nnl][3], key0 + col + 1) > th1);
                    }
                    unsigned ix0 = 0, ix1 = 0;
                    if (n0) ix0 = atomicAdd(&cntp[r0], (unsigned)n0);
                    if (n1) ix1 = atomicAdd(&cntp[r1], (unsigned)n1);
                    // pass 2: store survivors into reserved slots
#pragma unroll
                    for (int nnl = 0; nnl < 4; nnl++) {
                        const int col = cb + nnl * 8 + 2 * tig;
                        unsigned v0 = packscore(c[mm][nnl][0], key0 + col);
                        if (v0 > th0) svp[r0 * 128 + ix0++] = v0;
                        unsigned v1 = packscore(c[mm][nnl][1], key0 + col + 1);
                        if (v1 > th0) svp[r0 * 128 + ix0++] = v1;
                        unsigned v2 = packscore(c[mm][nnl][2], key0 + col);
                        if (v2 > th1) svp[r1 * 128 + ix1++] = v2;
                        unsigned v3 = packscore(c[mm][nnl][3], key0 + col + 1);
                        if (v3 > th1) svp[r1 * 128 + ix1++] = v3;
#pragma unroll
                        for (int r = 0; r < 4; r++) c[mm][nnl][r] = 0.f;
                    }
                }
                __threadfence_block();
                BAR_ARRIVE(1 + p, NTHREADS);                 // survivors(cc) ready
            }
        }
    } else {
        // =========================== scan warps ==========================
        const int q = tid - 256;                   // 0..63
        unsigned* h = hp + q * 33;
        unsigned hmin = 0; int minpos = 0;

        for (int cc = 0; cc < NCHUNK; cc++) {
            const int p = cc & 1;
            BAR_SYNC(1 + p, NTHREADS);             // survivors(cc) ready
            const int n = (int)cnt[p * QT + q];
            const unsigned* s = sv + p * SV_BUF + q * 128;
            for (int i = 0; i < n; i++) {
                unsigned v = s[i];
                if (v > hmin) { h[minpos] = v; rescan32(h, hmin, minpos); }
            }
            cnt[p * QT + q] = 0u;
            hminS[q] = hmin;
            __threadfence_block();
            BAR_ARRIVE(3 + p, NTHREADS);           // buffer p free
        }
    }
    __syncthreads();

    // ---- softmax over top-32 + fp16 value gather + fp32 residual ----
    // all 10 warps: q = wid, wid+10, ...
    {
        const __half* vbase = valh + (size_t)slot * NKEYS * VDIM;
        for (int q = wid; q < QT; q += 10) {
            const int qg_ = q0 + q;
            unsigned p = hp[q * 33 + lane];
            float s = unpackscore(p);
            int  ki = (int)(p & 0x1FFFu);
            float m = s;
#pragma unroll
            for (int o = 16; o; o >>= 1)
                m = fmaxf(m, __shfl_xor_sync(0xffffffffu, m, o));
            float e = __expf(s - m);
            float sum = e;
#pragma unroll
            for (int o = 16; o; o >>= 1) sum += __shfl_xor_sync(0xffffffffu, sum, o);
            float w = e / sum;

            float2 acc[2][4];
#pragma unroll
            for (int j = 0; j < 2; j++)
#pragma unroll
                for (int u = 0; u < 4; u++) acc[j][u] = make_float2(0.f, 0.f);

#pragma unroll 8
            for (int k = 0; k < TOPK; k++) {
                float wk = __shfl_sync(0xffffffffu, w, k);
                int   ik = __shfl_sync(0xffffffffu, ki, k);
                const uint4* vr = (const uint4*)(vbase + (size_t)ik * VDIM);
#pragma unroll
                for (int j = 0; j < 2; j++) {
                    uint4 u4 = vr[lane + j * 32];
                    unsigned uu[4] = {u4.x, u4.y, u4.z, u4.w};
#pragma unroll
                    for (int u = 0; u < 4; u++) {
                        float2 f = __half22float2(*(__half2*)&uu[u]);
                        acc[j][u].x += wk * f.x;
                        acc[j][u].y += wk * f.y;
                    }
                }
            }
            const float2* rr = (const float2*)(g_resid + (size_t)qg_ * VDIM);
            float2* op = (float2*)(out + ((size_t)qg_ * NSLOTS + slot) * VDIM);
#pragma unroll
            for (int j = 0; j < 2; j++)
#pragma unroll
                for (int u = 0; u < 4; u++) {
                    int idx = (lane + j * 32) * 4 + u;
                    float2 r = rr[idx];
                    op[idx] = make_float2(acc[j][u].x + r.x, acc[j][u].y + r.y);
                }
        }
    }
}

// ---------------------------------------------------------------------------
extern "C" void kernel_launch(void* const* d_in, const int* in_sizes, int n_in,
                              void* d_out, int out_size)
{
    const float* x      = (const float*)d_in[0];
    const float* keys   = (const float*)d_in[1];
    const float* values = (const float*)d_in[2];
    const float* wq     = (const float*)d_in[3];
    const float* bq     = (const float*)d_in[4];
    const float* wr     = (const float*)d_in[5];
    const float* br     = (const float*)d_in[6];
    float* out = (float*)d_out;

    float *qp, *rp;
    __half *kf, *vh;
    cudaGetSymbolAddress((void**)&qp, g_q);
    cudaGetSymbolAddress((void**)&rp, g_resid);
    cudaGetSymbolAddress((void**)&kf, g_keysf);
    cudaGetSymbolAddress((void**)&vh, g_valh);

    prep<<<8192 + NSLOTS * NKEYS * VDIM / (256 * 8), 256>>>(keys, values, kf, vh);
    gemm_nt_bias<<<dim3(KDIM / 64, NQ / 64), 128>>>(x, wq, bq, qp, NQ, KDIM, IN_DIM);
    gemm_nt_bias<<<dim3(VDIM / 64, NQ / 64), 128>>>(qp, wr, br, rp, NQ, VDIM, KDIM);

    cudaFuncSetAttribute(fused_slot,
                         cudaFuncAttributeMaxDynamicSharedMemorySize,
                         FUSED_SMEM_BYTES);
    fused_slot<<<dim3(NQ / QT, NSLOTS), NTHREADS, FUSED_SMEM_BYTES>>>(kf, vh, out);
}